// round 3
// baseline (speedup 1.0000x reference)
#include <cuda_runtime.h>
#include <math.h>
#include <limits.h>

// Problem constants (fixed by setup_inputs)
#define Nn   10000
#define Fin  2000
#define Hh   10
#define C1c  128
#define HID  1280          // Hh*C1c
#define C2c  64
#define HID2 640           // Hh*C2c
#define Ee   150000
#define ET   (Ee + Nn)     // edges + self loops
#define NEG  0.2f

// ---------------- scratch (device globals; no allocations) ----------------
__device__ float g_h1[Nn * HID];     // layer1 linear output h = xW1   (51.2 MB)
__device__ float g_agg1[Nn * HID];   // layer1 aggregation -> relu'd h1 (51.2 MB)
__device__ float g_h2[Nn * HID2];    // layer2 linear output           (25.6 MB)
__device__ float g_agg2[Nn * HID2];  // layer2 aggregation             (25.6 MB)
__device__ float g_as[Nn * Hh];
__device__ float g_ad[Nn * Hh];
__device__ int   g_max[Nn * Hh];     // ordered-int encoded float max
__device__ float g_den[Nn * Hh];
__device__ float g_ex[ET * Hh];      // exp(e - max) per edge/head     (6.4 MB)
__device__ int   g_src[Ee];          // decoded edge sources
__device__ int   g_dst[Ee];          // decoded edge destinations

// ---------------- helpers ----------------
__device__ __forceinline__ int f2ord(float f) {
    int b = __float_as_int(f);
    return b >= 0 ? b : (b ^ 0x7FFFFFFF);
}
__device__ __forceinline__ float ord2f(int k) {
    return __int_as_float(k >= 0 ? k : (k ^ 0x7FFFFFFF));
}

// ---------------- edge decode: auto-detect int32 vs int64 layout ----------------
// For int64 edge_index, node ids < 10000 => every odd 32-bit word (high half) is 0.
// For int32, odd words are random node ids (P(all 128 sampled == 0) ~ 1e-512).
__global__ void decode_edges_kernel(const unsigned int* __restrict__ w)
{
    __shared__ int is64;
    if (threadIdx.x == 0) {
        unsigned int nz = 0u;
#pragma unroll
        for (int i = 1; i < 257; i += 2) nz |= w[i];
        is64 = (nz == 0u) ? 1 : 0;
    }
    __syncthreads();
    int e = blockIdx.x * blockDim.x + threadIdx.x;
    if (e >= Ee) return;
    int s, d;
    if (is64) {
        s = (int)w[2 * e];
        d = (int)w[2 * (Ee + e)];
    } else {
        s = (int)w[e];
        d = (int)w[Ee + e];
    }
    // clamp: convert any misinterpretation into finite error instead of a trap
    s = s < 0 ? 0 : (s >= Nn ? Nn - 1 : s);
    d = d < 0 ? 0 : (d >= Nn ? Nn - 1 : d);
    g_src[e] = s;
    g_dst[e] = d;
}

// ---------------- SGEMM body: C[M,N] = A[M,K] * B[K,N], fp32, 128x128x8 ----------------
__device__ __forceinline__ void sgemm_body(const float* __restrict__ A,
                                           const float* __restrict__ B,
                                           float* __restrict__ C,
                                           int M, int N, int K)
{
    __shared__ float As[8][128];
    __shared__ float Bs[8][128];

    const int tid = threadIdx.x;
    const int m0 = blockIdx.y * 128;
    const int n0 = blockIdx.x * 128;

    const int arow = tid >> 1;           // 0..127
    const int acol = (tid & 1) * 4;      // 0 or 4
    const int brow = tid >> 5;           // 0..7
    const int bcol = (tid & 31) * 4;     // 0..124

    const int tx = tid & 15;             // N-dir micro index
    const int ty = tid >> 4;             // M-dir micro index

    const bool aval = (m0 + arow) < M;
    const float* Aptr = A + (long long)(m0 + arow) * K + acol;
    const float* Bptr = B + (long long)brow * N + n0 + bcol;

    float acc[8][8];
#pragma unroll
    for (int i = 0; i < 8; i++)
#pragma unroll
        for (int j = 0; j < 8; j++) acc[i][j] = 0.f;

    for (int k0 = 0; k0 < K; k0 += 8) {
        float4 av = aval ? *(const float4*)(Aptr + k0) : make_float4(0.f, 0.f, 0.f, 0.f);
        float4 bv = *(const float4*)(Bptr + (long long)k0 * N);

        __syncthreads();  // previous iteration's reads complete
        As[acol + 0][arow] = av.x;
        As[acol + 1][arow] = av.y;
        As[acol + 2][arow] = av.z;
        As[acol + 3][arow] = av.w;
        *(float4*)&Bs[brow][bcol] = bv;
        __syncthreads();

#pragma unroll
        for (int k = 0; k < 8; k++) {
            float a[8], b[8];
            *(float4*)(a)     = *(const float4*)&As[k][ty * 8];
            *(float4*)(a + 4) = *(const float4*)&As[k][ty * 8 + 4];
            *(float4*)(b)     = *(const float4*)&Bs[k][tx * 8];
            *(float4*)(b + 4) = *(const float4*)&Bs[k][tx * 8 + 4];
#pragma unroll
            for (int i = 0; i < 8; i++)
#pragma unroll
                for (int j = 0; j < 8; j++) acc[i][j] = fmaf(a[i], b[j], acc[i][j]);
        }
    }

#pragma unroll
    for (int i = 0; i < 8; i++) {
        int m = m0 + ty * 8 + i;
        if (m < M) {
            float* cp = C + (long long)m * N + n0 + tx * 8;
            *(float4*)(cp)     = make_float4(acc[i][0], acc[i][1], acc[i][2], acc[i][3]);
            *(float4*)(cp + 4) = make_float4(acc[i][4], acc[i][5], acc[i][6], acc[i][7]);
        }
    }
}

// GEMM wrappers binding __device__ scratch at compile time
__global__ void __launch_bounds__(256) sgemm_l1(const float* __restrict__ x,
                                                const float* __restrict__ W1)
{
    sgemm_body(x, W1, g_h1, Nn, HID, Fin);
}

__global__ void __launch_bounds__(256) sgemm_l2(const float* __restrict__ W2)
{
    sgemm_body(g_agg1, W2, g_h2, Nn, HID2, HID);
}

// ---------------- per-(node,head) attention logits ----------------
__device__ __forceinline__ void alphas_body(const float* __restrict__ h,
                                            const float* __restrict__ a_s,
                                            const float* __restrict__ a_d, int C)
{
    int w = (blockIdx.x * blockDim.x + threadIdx.x) >> 5;
    int lane = threadIdx.x & 31;
    if (w >= Nn * Hh) return;
    int n = w / Hh, hd = w % Hh;
    const float* hp  = h   + (long long)n * Hh * C + hd * C;
    const float* asp = a_s + hd * C;
    const float* adp = a_d + hd * C;
    float ss = 0.f, sd = 0.f;
    for (int c = lane; c < C; c += 32) {
        float v = hp[c];
        ss = fmaf(v, asp[c], ss);
        sd = fmaf(v, adp[c], sd);
    }
#pragma unroll
    for (int o = 16; o > 0; o >>= 1) {
        ss += __shfl_xor_sync(0xffffffffu, ss, o);
        sd += __shfl_xor_sync(0xffffffffu, sd, o);
    }
    if (lane == 0) { g_as[w] = ss; g_ad[w] = sd; }
}

__global__ void alphas1_kernel(const float* __restrict__ a_s,
                               const float* __restrict__ a_d)
{
    alphas_body(g_h1, a_s, a_d, C1c);
}

__global__ void alphas2_kernel(const float* __restrict__ a_s,
                               const float* __restrict__ a_d)
{
    alphas_body(g_h2, a_s, a_d, C2c);
}

// ---------------- init / zero ----------------
__global__ void initmd_kernel()
{
    int i = blockIdx.x * blockDim.x + threadIdx.x;
    if (i < Nn * Hh) { g_max[i] = INT_MIN; g_den[i] = 0.f; }
}

__global__ void zero_agg1_kernel()
{
    int i = blockIdx.x * blockDim.x + threadIdx.x;
    if (i < Nn * HID) g_agg1[i] = 0.f;
}

__global__ void zero_agg2_kernel()
{
    int i = blockIdx.x * blockDim.x + threadIdx.x;
    if (i < Nn * HID2) g_agg2[i] = 0.f;
}

// ---------------- edge passes (includes N implicit self loops) ----------------
__global__ void edge_max_kernel()
{
    int e = blockIdx.x * blockDim.x + threadIdx.x;
    if (e >= ET) return;
    int s, d;
    if (e < Ee) { s = g_src[e]; d = g_dst[e]; }
    else        { s = d = e - Ee; }
#pragma unroll
    for (int hh = 0; hh < Hh; hh++) {
        float v = g_as[s * Hh + hh] + g_ad[d * Hh + hh];
        v = v > 0.f ? v : NEG * v;
        atomicMax(&g_max[d * Hh + hh], f2ord(v));
    }
}

__global__ void edge_exp_kernel()
{
    int e = blockIdx.x * blockDim.x + threadIdx.x;
    if (e >= ET) return;
    int s, d;
    if (e < Ee) { s = g_src[e]; d = g_dst[e]; }
    else        { s = d = e - Ee; }
#pragma unroll
    for (int hh = 0; hh < Hh; hh++) {
        float v = g_as[s * Hh + hh] + g_ad[d * Hh + hh];
        v = v > 0.f ? v : NEG * v;
        float m = ord2f(g_max[d * Hh + hh]);
        float ex = expf(v - m);
        g_ex[e * Hh + hh] = ex;
        atomicAdd(&g_den[d * Hh + hh], ex);
    }
}

// ---------------- scatter (real edges only; self loop folded into finalize) ----------------
// layer 1: one warp per (edge, head), 32 lanes x float4 = 128 channels
__global__ void scatter1_kernel()
{
    int w = (blockIdx.x * blockDim.x + threadIdx.x) >> 5;
    int lane = threadIdx.x & 31;
    if (w >= Ee * Hh) return;
    int e = w / Hh, hh = w % Hh;
    int s = g_src[e], d = g_dst[e];
    float alpha = g_ex[e * Hh + hh] / (g_den[d * Hh + hh] + 1e-16f);
    const float4* src = (const float4*)(g_h1 + (long long)s * HID + hh * C1c);
    float* dst = g_agg1 + (long long)d * HID + hh * C1c + lane * 4;
    float4 v = src[lane];
    atomicAdd(dst + 0, v.x * alpha);
    atomicAdd(dst + 1, v.y * alpha);
    atomicAdd(dst + 2, v.z * alpha);
    atomicAdd(dst + 3, v.w * alpha);
}

// layer 2: one warp per (edge, head-pair); 16 lanes x float4 = 64 channels per head
__global__ void scatter2_kernel()
{
    int w = (blockIdx.x * blockDim.x + threadIdx.x) >> 5;
    int lane = threadIdx.x & 31;
    if (w >= Ee * (Hh / 2)) return;
    int e = w / (Hh / 2), p = w % (Hh / 2);
    int hh = p * 2 + (lane >> 4);
    int c4 = lane & 15;
    int s = g_src[e], d = g_dst[e];
    float alpha = g_ex[e * Hh + hh] / (g_den[d * Hh + hh] + 1e-16f);
    const float4* src = (const float4*)(g_h2 + (long long)s * HID2 + hh * C2c);
    float* dst = g_agg2 + (long long)d * HID2 + hh * C2c + c4 * 4;
    float4 v = src[c4];
    atomicAdd(dst + 0, v.x * alpha);
    atomicAdd(dst + 1, v.y * alpha);
    atomicAdd(dst + 2, v.z * alpha);
    atomicAdd(dst + 3, v.w * alpha);
}

// ---------------- finalize ----------------
// layer1: add self-loop contribution + bias, relu; result (next layer input) in g_agg1
__global__ void final1_kernel(const float* __restrict__ b1)
{
    int i = blockIdx.x * blockDim.x + threadIdx.x;
    if (i >= Nn * HID) return;
    int n = i / HID, f = i % HID, hh = f / C1c;
    float aself = g_ex[(Ee + n) * Hh + hh] / (g_den[n * Hh + hh] + 1e-16f);
    float v = g_agg1[i] + g_h1[i] * aself + b1[f];
    g_agg1[i] = v > 0.f ? v : 0.f;
}

// layer2: self loop + mean over heads + bias + relu -> d_out
__global__ void final2_kernel(const float* __restrict__ b2, float* __restrict__ out)
{
    int i = blockIdx.x * blockDim.x + threadIdx.x;
    if (i >= Nn * C2c) return;
    int n = i / C2c, l = i % C2c;
    float sum = 0.f;
#pragma unroll
    for (int hh = 0; hh < Hh; hh++) {
        float aself = g_ex[(Ee + n) * Hh + hh] / (g_den[n * Hh + hh] + 1e-16f);
        int idx = n * HID2 + hh * C2c + l;
        sum += g_agg2[idx] + g_h2[idx] * aself;
    }
    float v = sum * (1.0f / Hh) + b2[l];
    out[i] = v > 0.f ? v : 0.f;
}

// ---------------- launch ----------------
extern "C" void kernel_launch(void* const* d_in, const int* in_sizes, int n_in,
                              void* d_out, int out_size)
{
    const float*        x      = (const float*)d_in[0];
    const unsigned int* ei_raw = (const unsigned int*)d_in[1];
    const float*        W1     = (const float*)d_in[2];
    const float*        a_src1 = (const float*)d_in[3];
    const float*        a_dst1 = (const float*)d_in[4];
    const float*        b1     = (const float*)d_in[5];
    const float*        W2     = (const float*)d_in[6];
    const float*        a_src2 = (const float*)d_in[7];
    const float*        a_dst2 = (const float*)d_in[8];
    const float*        b2     = (const float*)d_in[9];
    float* out = (float*)d_out;

    const int TB = 256;

    // ---------- decode edges once (dtype auto-detect, clamped) ----------
    decode_edges_kernel<<<(Ee + TB - 1) / TB, TB>>>(ei_raw);

    // ---------- layer 1 ----------
    initmd_kernel<<<(Nn * Hh + TB - 1) / TB, TB>>>();
    zero_agg1_kernel<<<(Nn * HID + TB - 1) / TB, TB>>>();

    {
        dim3 grid(HID / 128, (Nn + 127) / 128);
        sgemm_l1<<<grid, 256>>>(x, W1);
    }

    alphas1_kernel<<<(Nn * Hh * 32 + TB - 1) / TB, TB>>>(a_src1, a_dst1);
    edge_max_kernel<<<(ET + TB - 1) / TB, TB>>>();
    edge_exp_kernel<<<(ET + TB - 1) / TB, TB>>>();
    scatter1_kernel<<<(int)(((long long)Ee * Hh * 32 + TB - 1) / TB), TB>>>();
    final1_kernel<<<(Nn * HID + TB - 1) / TB, TB>>>(b1);

    // ---------- layer 2 ----------
    initmd_kernel<<<(Nn * Hh + TB - 1) / TB, TB>>>();
    zero_agg2_kernel<<<(Nn * HID2 + TB - 1) / TB, TB>>>();

    {
        dim3 grid(HID2 / 128, (Nn + 127) / 128);
        sgemm_l2<<<grid, 256>>>(W2);
    }

    alphas2_kernel<<<(Nn * Hh * 32 + TB - 1) / TB, TB>>>(a_src2, a_dst2);
    edge_max_kernel<<<(ET + TB - 1) / TB, TB>>>();
    edge_exp_kernel<<<(ET + TB - 1) / TB, TB>>>();
    scatter2_kernel<<<(int)(((long long)Ee * (Hh / 2) * 32 + TB - 1) / TB), TB>>>();
    final2_kernel<<<(Nn * C2c + TB - 1) / TB, TB>>>(b2, out);
}

// round 5
// speedup vs baseline: 1.5086x; 1.5086x over previous
#include <cuda_runtime.h>
#include <cuda_bf16.h>
#include <math.h>
#include <limits.h>
#include <stdint.h>

// Problem constants (fixed by setup_inputs)
#define Nn   10000
#define Fin  2000
#define Hh   10
#define C1c  128
#define HID  1280          // Hh*C1c
#define C2c  64
#define HID2 640           // Hh*C2c
#define Ee   150000
#define ET   (Ee + Nn)     // edges + self loops
#define NEG  0.2f

// K-extended split dims: [hi | hi | lo] x [hi | lo | hi]
#define KP1  6144          // 3 * 2048 (Fin=2000 padded to 2048)
#define KS1  2048
#define KP2  3840          // 3 * 1280
#define KS2  1280

// ---------------- scratch (device globals; no allocations) ----------------
__device__ float g_h1[Nn * HID];
__device__ float g_agg1[Nn * HID];
__device__ float g_h2[Nn * HID2];
__device__ float g_agg2[Nn * HID2];
__device__ float g_as[Nn * Hh];
__device__ float g_ad[Nn * Hh];
__device__ int   g_max[Nn * Hh];
__device__ float g_den[Nn * Hh];
__device__ float g_ex[ET * Hh];
__device__ int   g_src[Ee];
__device__ int   g_dst[Ee];

// K-extended bf16 operands
__device__ __nv_bfloat16 g_xs[(size_t)Nn * KP1];     // A' layer1 (122.9 MB)
__device__ __nv_bfloat16 g_w1s[(size_t)HID * KP1];   // B' layer1 = W1^T ext (15.7 MB)
__device__ __nv_bfloat16 g_a2s[(size_t)Nn * KP2];    // A' layer2 (76.8 MB)
__device__ __nv_bfloat16 g_w2s[(size_t)HID2 * KP2];  // B' layer2 (4.9 MB)

// ---------------- portable PTX helpers (sm_80+ ISA only) ----------------
__device__ __forceinline__ uint32_t smem_u32(const void* p) {
    uint32_t a;
    asm("{ .reg .u64 t; cvta.to.shared.u64 t, %1; cvt.u32.u64 %0, t; }"
        : "=r"(a) : "l"(p));
    return a;
}
__device__ __forceinline__ void cp16(uint32_t dst, const void* src, int sz) {
    asm volatile("cp.async.cg.shared.global [%0], [%1], 16, %2;"
                 :: "r"(dst), "l"(src), "r"(sz) : "memory");
}
__device__ __forceinline__ void cp_commit() {
    asm volatile("cp.async.commit_group;" ::: "memory");
}
template<int W> __device__ __forceinline__ void cp_wait() {
    asm volatile("cp.async.wait_group %0;" :: "n"(W) : "memory");
}
__device__ __forceinline__ void ldsm_x4(uint32_t& r0, uint32_t& r1, uint32_t& r2,
                                        uint32_t& r3, uint32_t addr) {
    asm volatile("ldmatrix.sync.aligned.m8n8.x4.shared.b16 {%0,%1,%2,%3}, [%4];"
                 : "=r"(r0), "=r"(r1), "=r"(r2), "=r"(r3) : "r"(addr));
}
__device__ __forceinline__ void mma16816(float* c, const uint32_t* a, const uint32_t* b) {
    asm volatile("mma.sync.aligned.m16n8k16.row.col.f32.bf16.bf16.f32 "
                 "{%0,%1,%2,%3}, {%4,%5,%6,%7}, {%8,%9}, {%0,%1,%2,%3};"
                 : "+f"(c[0]), "+f"(c[1]), "+f"(c[2]), "+f"(c[3])
                 : "r"(a[0]), "r"(a[1]), "r"(a[2]), "r"(a[3]), "r"(b[0]), "r"(b[1]));
}

// ---------------- bf16 mma GEMM: C[M][Ntot] += A'[M][Kp] * B'[Ntot][Kp]^T ----------------
// Block 128x128x32, 2-stage cp.async, 8 warps of 64x32.
// smem per stage: A 128x40 b16 + B 128x40 b16 (stride 40 avoids bank conflicts).
#define SROW 40
#define STAGE_B16 (2 * 128 * SROW)   // A+B one stage, in b16 units (10240)

template<int Kp, int Ntot>
__device__ __forceinline__ void mma_gemm_body(const __nv_bfloat16* __restrict__ A,
                                              const __nv_bfloat16* __restrict__ B,
                                              float* __restrict__ C, int M)
{
    __shared__ __align__(16) __nv_bfloat16 smem[2 * STAGE_B16];
    const uint32_t sbase = smem_u32(smem);
    const int tid = threadIdx.x;
    const int wid = tid >> 5, lane = tid & 31;
    const int wm = wid & 1, wn = wid >> 1;      // 2 x 4 warp grid
    const int m0 = blockIdx.y * 128, n0 = blockIdx.x * 128;
    const int NC = Kp / 32;

    float acc[4][4][4];
#pragma unroll
    for (int i = 0; i < 4; i++)
#pragma unroll
        for (int j = 0; j < 4; j++)
#pragma unroll
            for (int q = 0; q < 4; q++) acc[i][j][q] = 0.f;

    const int lr = tid >> 2;             // 0..63
    const int lc = (tid & 3) * 8;        // 0,8,16,24

#define LOADC(c)                                                                  \
    {                                                                             \
        const int s_ = (c) & 1;                                                   \
        const int k0_ = (c) * 32;                                                 \
        const uint32_t sA_ = sbase + (uint32_t)(s_ * STAGE_B16) * 2u;             \
        const uint32_t sB_ = sA_ + 128u * SROW * 2u;                              \
        _Pragma("unroll")                                                         \
        for (int p = 0; p < 2; p++) {                                             \
            const int row = lr + p * 64;                                          \
            const int m = m0 + row;                                               \
            const int mc = m < M ? m : (M - 1);                                   \
            cp16(sA_ + (uint32_t)(row * SROW + lc) * 2u,                          \
                 A + (size_t)mc * Kp + k0_ + lc, m < M ? 16 : 0);                 \
        }                                                                         \
        _Pragma("unroll")                                                         \
        for (int p = 0; p < 2; p++) {                                             \
            const int row = lr + p * 64;                                          \
            cp16(sB_ + (uint32_t)(row * SROW + lc) * 2u,                          \
                 B + (size_t)(n0 + row) * Kp + k0_ + lc, 16);                     \
        }                                                                         \
        cp_commit();                                                              \
    }

    LOADC(0);
    if (NC > 1) LOADC(1);

    for (int c = 0; c < NC; c++) {
        if (c + 1 < NC) cp_wait<1>(); else cp_wait<0>();
        __syncthreads();

        const int s = c & 1;
        const uint32_t sA = sbase + (uint32_t)(s * STAGE_B16) * 2u;
        const uint32_t sB = sA + 128u * SROW * 2u;

#pragma unroll
        for (int ks = 0; ks < 2; ks++) {
            const int kk = ks * 16;
            uint32_t af[4][4];
#pragma unroll
            for (int mt = 0; mt < 4; mt++) {
                const int row = wm * 64 + mt * 16 + (lane & 15);
                const int col = kk + ((lane >> 4) << 3);
                ldsm_x4(af[mt][0], af[mt][1], af[mt][2], af[mt][3],
                        sA + (uint32_t)(row * SROW + col) * 2u);
            }
            uint32_t bf[4][2];
#pragma unroll
            for (int g = 0; g < 2; g++) {
                const int row = wn * 32 + g * 16 + (lane & 7) + ((lane >> 4) << 3);
                const int col = kk + (((lane >> 3) & 1) << 3);
                uint32_t r0, r1, r2, r3;
                ldsm_x4(r0, r1, r2, r3, sB + (uint32_t)(row * SROW + col) * 2u);
                bf[2 * g][0] = r0; bf[2 * g][1] = r1;
                bf[2 * g + 1][0] = r2; bf[2 * g + 1][1] = r3;
            }
#pragma unroll
            for (int mt = 0; mt < 4; mt++)
#pragma unroll
                for (int nt = 0; nt < 4; nt++)
                    mma16816(acc[mt][nt], af[mt], bf[nt]);
        }
        __syncthreads();
        if (c + 2 < NC) LOADC(c + 2);
    }
#undef LOADC

    // epilogue
#pragma unroll
    for (int mt = 0; mt < 4; mt++) {
        const int r0 = m0 + wm * 64 + mt * 16 + (lane >> 2);
#pragma unroll
        for (int nt = 0; nt < 4; nt++) {
            const int cc = n0 + wn * 32 + nt * 8 + (lane & 3) * 2;
            if (r0 < M) {
                C[(size_t)r0 * Ntot + cc]     = acc[mt][nt][0];
                C[(size_t)r0 * Ntot + cc + 1] = acc[mt][nt][1];
            }
            if (r0 + 8 < M) {
                C[(size_t)(r0 + 8) * Ntot + cc]     = acc[mt][nt][2];
                C[(size_t)(r0 + 8) * Ntot + cc + 1] = acc[mt][nt][3];
            }
        }
    }
}

__global__ void __launch_bounds__(256) gemm1_mma() {
    mma_gemm_body<KP1, HID>(g_xs, g_w1s, g_h1, Nn);
}
__global__ void __launch_bounds__(256) gemm2_mma() {
    mma_gemm_body<KP2, HID2>(g_a2s, g_w2s, g_h2, Nn);
}

// ---------------- fp32 -> bf16 hi/lo split ----------------
__device__ __forceinline__ void split_bf16(float f, __nv_bfloat16& hi, __nv_bfloat16& lo) {
    hi = __float2bfloat16(f);
    lo = __float2bfloat16(f - __bfloat162float(hi));
}

// x -> A' [hi@0 | hi@KS1 | lo@2KS1]
__global__ void conv_x_kernel(const float* __restrict__ x) {
    int i = blockIdx.x * blockDim.x + threadIdx.x;
    if (i >= Nn * KS1) return;
    int n = i / KS1, k = i % KS1;
    float f = (k < Fin) ? x[(size_t)n * Fin + k] : 0.f;
    __nv_bfloat16 hi, lo; split_bf16(f, hi, lo);
    size_t base = (size_t)n * KP1;
    g_xs[base + k] = hi;
    g_xs[base + KS1 + k] = hi;
    g_xs[base + 2 * KS1 + k] = lo;
}

// relu(h1)=g_agg1 -> A' layer2 [hi | hi | lo]
__global__ void conv_a2_kernel() {
    int i = blockIdx.x * blockDim.x + threadIdx.x;
    if (i >= Nn * KS2) return;
    int n = i / KS2, k = i % KS2;
    float f = g_agg1[(size_t)n * KS2 + k];
    __nv_bfloat16 hi, lo; split_bf16(f, hi, lo);
    size_t base = (size_t)n * KP2;
    g_a2s[base + k] = hi;
    g_a2s[base + KS2 + k] = hi;
    g_a2s[base + 2 * KS2 + k] = lo;
}

// W [K][N] -> B' [N][Kp] with [hi@0 | lo@KS | hi@2KS]
template<int K, int KS, int KPv, int N>
__device__ __forceinline__ void convT_body(const float* __restrict__ in,
                                           __nv_bfloat16* __restrict__ outp)
{
    __shared__ float t[32][33];
    const int kb = blockIdx.x * 32, nb = blockIdx.y * 32;
    const int tx = threadIdx.x, ty = threadIdx.y;
#pragma unroll
    for (int j = 0; j < 4; j++) {
        int k = kb + ty + j * 8;
        t[ty + j * 8][tx] = (k < K) ? in[(size_t)k * N + nb + tx] : 0.f;
    }
    __syncthreads();
#pragma unroll
    for (int j = 0; j < 4; j++) {
        int n = nb + ty + j * 8;
        int k = kb + tx;
        __nv_bfloat16 hi, lo;
        split_bf16(t[tx][ty + j * 8], hi, lo);
        size_t base = (size_t)n * KPv;
        outp[base + k] = hi;
        outp[base + KS + k] = lo;
        outp[base + 2 * KS + k] = hi;
    }
}
__global__ void convT1_kernel(const float* __restrict__ W1) {
    convT_body<Fin, KS1, KP1, HID>(W1, g_w1s);
}
__global__ void convT2_kernel(const float* __restrict__ W2) {
    convT_body<HID, KS2, KP2, HID2>(W2, g_w2s);
}

// ---------------- helpers ----------------
__device__ __forceinline__ int f2ord(float f) {
    int b = __float_as_int(f);
    return b >= 0 ? b : (b ^ 0x7FFFFFFF);
}
__device__ __forceinline__ float ord2f(int k) {
    return __int_as_float(k >= 0 ? k : (k ^ 0x7FFFFFFF));
}

// ---------------- edge decode (int32/int64 auto-detect) ----------------
__global__ void decode_edges_kernel(const unsigned int* __restrict__ w)
{
    __shared__ int is64;
    if (threadIdx.x == 0) {
        unsigned int nz = 0u;
#pragma unroll
        for (int i = 1; i < 257; i += 2) nz |= w[i];
        is64 = (nz == 0u) ? 1 : 0;
    }
    __syncthreads();
    int e = blockIdx.x * blockDim.x + threadIdx.x;
    if (e >= Ee) return;
    int s, d;
    if (is64) { s = (int)w[2 * e]; d = (int)w[2 * (Ee + e)]; }
    else      { s = (int)w[e];     d = (int)w[Ee + e]; }
    s = s < 0 ? 0 : (s >= Nn ? Nn - 1 : s);
    d = d < 0 ? 0 : (d >= Nn ? Nn - 1 : d);
    g_src[e] = s;
    g_dst[e] = d;
}

// ---------------- per-(node,head) attention logits ----------------
__device__ __forceinline__ void alphas_body(const float* __restrict__ h,
                                            const float* __restrict__ a_s,
                                            const float* __restrict__ a_d, int C)
{
    int w = (blockIdx.x * blockDim.x + threadIdx.x) >> 5;
    int lane = threadIdx.x & 31;
    if (w >= Nn * Hh) return;
    int n = w / Hh, hd = w % Hh;
    const float* hp  = h   + (long long)n * Hh * C + hd * C;
    const float* asp = a_s + hd * C;
    const float* adp = a_d + hd * C;
    float ss = 0.f, sd = 0.f;
    for (int c = lane; c < C; c += 32) {
        float v = hp[c];
        ss = fmaf(v, asp[c], ss);
        sd = fmaf(v, adp[c], sd);
    }
#pragma unroll
    for (int o = 16; o > 0; o >>= 1) {
        ss += __shfl_xor_sync(0xffffffffu, ss, o);
        sd += __shfl_xor_sync(0xffffffffu, sd, o);
    }
    if (lane == 0) { g_as[w] = ss; g_ad[w] = sd; }
}

__global__ void alphas1_kernel(const float* __restrict__ a_s, const float* __restrict__ a_d) {
    alphas_body(g_h1, a_s, a_d, C1c);
}
__global__ void alphas2_kernel(const float* __restrict__ a_s, const float* __restrict__ a_d) {
    alphas_body(g_h2, a_s, a_d, C2c);
}

// ---------------- init / zero ----------------
__global__ void initmd_kernel() {
    int i = blockIdx.x * blockDim.x + threadIdx.x;
    if (i < Nn * Hh) { g_max[i] = INT_MIN; g_den[i] = 0.f; }
}
__global__ void zero_agg1_kernel() {
    int i = blockIdx.x * blockDim.x + threadIdx.x;
    if (i < Nn * HID) g_agg1[i] = 0.f;
}
__global__ void zero_agg2_kernel() {
    int i = blockIdx.x * blockDim.x + threadIdx.x;
    if (i < Nn * HID2) g_agg2[i] = 0.f;
}

// ---------------- edge passes ----------------
__global__ void edge_max_kernel()
{
    int e = blockIdx.x * blockDim.x + threadIdx.x;
    if (e >= ET) return;
    int s, d;
    if (e < Ee) { s = g_src[e]; d = g_dst[e]; }
    else        { s = d = e - Ee; }
#pragma unroll
    for (int hh = 0; hh < Hh; hh++) {
        float v = g_as[s * Hh + hh] + g_ad[d * Hh + hh];
        v = v > 0.f ? v : NEG * v;
        atomicMax(&g_max[d * Hh + hh], f2ord(v));
    }
}

__global__ void edge_exp_kernel()
{
    int e = blockIdx.x * blockDim.x + threadIdx.x;
    if (e >= ET) return;
    int s, d;
    if (e < Ee) { s = g_src[e]; d = g_dst[e]; }
    else        { s = d = e - Ee; }
#pragma unroll
    for (int hh = 0; hh < Hh; hh++) {
        float v = g_as[s * Hh + hh] + g_ad[d * Hh + hh];
        v = v > 0.f ? v : NEG * v;
        float m = ord2f(g_max[d * Hh + hh]);
        float ex = expf(v - m);
        g_ex[e * Hh + hh] = ex;
        atomicAdd(&g_den[d * Hh + hh], ex);
    }
}

// ---------------- scatter ----------------
__global__ void scatter1_kernel()
{
    int w = (blockIdx.x * blockDim.x + threadIdx.x) >> 5;
    int lane = threadIdx.x & 31;
    if (w >= Ee * Hh) return;
    int e = w / Hh, hh = w % Hh;
    int s = g_src[e], d = g_dst[e];
    float alpha = g_ex[e * Hh + hh] / (g_den[d * Hh + hh] + 1e-16f);
    const float4* src = (const float4*)(g_h1 + (long long)s * HID + hh * C1c);
    float* dst = g_agg1 + (long long)d * HID + hh * C1c + lane * 4;
    float4 v = src[lane];
    atomicAdd(dst + 0, v.x * alpha);
    atomicAdd(dst + 1, v.y * alpha);
    atomicAdd(dst + 2, v.z * alpha);
    atomicAdd(dst + 3, v.w * alpha);
}

__global__ void scatter2_kernel()
{
    int w = (blockIdx.x * blockDim.x + threadIdx.x) >> 5;
    int lane = threadIdx.x & 31;
    if (w >= Ee * (Hh / 2)) return;
    int e = w / (Hh / 2), p = w % (Hh / 2);
    int hh = p * 2 + (lane >> 4);
    int c4 = lane & 15;
    int s = g_src[e], d = g_dst[e];
    float alpha = g_ex[e * Hh + hh] / (g_den[d * Hh + hh] + 1e-16f);
    const float4* src = (const float4*)(g_h2 + (long long)s * HID2 + hh * C2c);
    float* dst = g_agg2 + (long long)d * HID2 + hh * C2c + c4 * 4;
    float4 v = src[c4];
    atomicAdd(dst + 0, v.x * alpha);
    atomicAdd(dst + 1, v.y * alpha);
    atomicAdd(dst + 2, v.z * alpha);
    atomicAdd(dst + 3, v.w * alpha);
}

// ---------------- finalize ----------------
__global__ void final1_kernel(const float* __restrict__ b1)
{
    int i = blockIdx.x * blockDim.x + threadIdx.x;
    if (i >= Nn * HID) return;
    int n = i / HID, f = i % HID, hh = f / C1c;
    float aself = g_ex[(Ee + n) * Hh + hh] / (g_den[n * Hh + hh] + 1e-16f);
    float v = g_agg1[i] + g_h1[i] * aself + b1[f];
    g_agg1[i] = v > 0.f ? v : 0.f;
}

__global__ void final2_kernel(const float* __restrict__ b2, float* __restrict__ out)
{
    int i = blockIdx.x * blockDim.x + threadIdx.x;
    if (i >= Nn * C2c) return;
    int n = i / C2c, l = i % C2c;
    float sum = 0.f;
#pragma unroll
    for (int hh = 0; hh < Hh; hh++) {
        float aself = g_ex[(Ee + n) * Hh + hh] / (g_den[n * Hh + hh] + 1e-16f);
        int idx = n * HID2 + hh * C2c + l;
        sum += g_agg2[idx] + g_h2[idx] * aself;
    }
    float v = sum * (1.0f / Hh) + b2[l];
    out[i] = v > 0.f ? v : 0.f;
}

// ---------------- launch ----------------
extern "C" void kernel_launch(void* const* d_in, const int* in_sizes, int n_in,
                              void* d_out, int out_size)
{
    const float*        x      = (const float*)d_in[0];
    const unsigned int* ei_raw = (const unsigned int*)d_in[1];
    const float*        W1     = (const float*)d_in[2];
    const float*        a_src1 = (const float*)d_in[3];
    const float*        a_dst1 = (const float*)d_in[4];
    const float*        b1     = (const float*)d_in[5];
    const float*        W2     = (const float*)d_in[6];
    const float*        a_src2 = (const float*)d_in[7];
    const float*        a_dst2 = (const float*)d_in[8];
    const float*        b2     = (const float*)d_in[9];
    float* out = (float*)d_out;

    const int TB = 256;

    // ---------- decode + operand prep ----------
    decode_edges_kernel<<<(Ee + TB - 1) / TB, TB>>>(ei_raw);
    conv_x_kernel<<<(Nn * KS1 + TB - 1) / TB, TB>>>(x);
    {
        dim3 blk(32, 8);
        dim3 g1(KS1 / 32, HID / 32);
        convT1_kernel<<<g1, blk>>>(W1);
    }

    // ---------- layer 1 ----------
    initmd_kernel<<<(Nn * Hh + TB - 1) / TB, TB>>>();
    zero_agg1_kernel<<<(Nn * HID + TB - 1) / TB, TB>>>();

    {
        dim3 grid(HID / 128, (Nn + 127) / 128);
        gemm1_mma<<<grid, 256>>>();
    }

    alphas1_kernel<<<(Nn * Hh * 32 + TB - 1) / TB, TB>>>(a_src1, a_dst1);
    edge_max_kernel<<<(ET + TB - 1) / TB, TB>>>();
    edge_exp_kernel<<<(ET + TB - 1) / TB, TB>>>();
    scatter1_kernel<<<(int)(((long long)Ee * Hh * 32 + TB - 1) / TB), TB>>>();
    final1_kernel<<<(Nn * HID + TB - 1) / TB, TB>>>(b1);

    // ---------- layer 2 prep ----------
    conv_a2_kernel<<<(Nn * KS2 + TB - 1) / TB, TB>>>();
    {
        dim3 blk(32, 8);
        dim3 g2(KS2 / 32, HID2 / 32);
        convT2_kernel<<<g2, blk>>>(W2);
    }

    initmd_kernel<<<(Nn * Hh + TB - 1) / TB, TB>>>();
    zero_agg2_kernel<<<(Nn * HID2 + TB - 1) / TB, TB>>>();

    {
        dim3 grid(HID2 / 128, (Nn + 127) / 128);
        gemm2_mma<<<grid, 256>>>();
    }

    alphas2_kernel<<<(Nn * Hh * 32 + TB - 1) / TB, TB>>>(a_src2, a_dst2);
    edge_max_kernel<<<(ET + TB - 1) / TB, TB>>>();
    edge_exp_kernel<<<(ET + TB - 1) / TB, TB>>>();
    scatter2_kernel<<<(int)(((long long)Ee * (Hh / 2) * 32 + TB - 1) / TB), TB>>>();
    final2_kernel<<<(Nn * C2c + TB - 1) / TB, TB>>>(b2, out);
}

// round 6
// speedup vs baseline: 2.9313x; 1.9430x over previous
#include <cuda_runtime.h>
#include <cuda_bf16.h>
#include <math.h>
#include <limits.h>
#include <stdint.h>

// Problem constants (fixed by setup_inputs)
#define Nn   10000
#define Fin  2000
#define Hh   10
#define C1c  128
#define HID  1280          // Hh*C1c
#define C2c  64
#define HID2 640           // Hh*C2c
#define Ee   150000
#define NEG  0.2f

#define KS1  2048          // Fin padded
#define KS2  1280          // = HID

// ---------------- scratch (device globals; no allocations) ----------------
__device__ float g_h1[Nn * HID];     // layer1 linear output
__device__ float g_h2[Nn * HID2];    // layer2 linear output
__device__ float g_agg2[Nn * HID2];  // layer2 per-head aggregation (incl self)
__device__ float g_as[Nn * Hh];
__device__ float g_ad[Nn * Hh];
__device__ int   g_src[Ee];
__device__ int   g_dst[Ee];
__device__ int   g_deg[Nn];
__device__ int   g_rowptr[Nn + 1];
__device__ int   g_cursor[Nn];
__device__ int   g_esrc[Ee];         // CSR: incoming-edge sources per dst

// bf16 split operands
__device__ __nv_bfloat16 g_xhi[(size_t)Nn * KS1],  g_xlo[(size_t)Nn * KS1];
__device__ __nv_bfloat16 g_w1hi[(size_t)HID * KS1], g_w1lo[(size_t)HID * KS1];
__device__ __nv_bfloat16 g_a2hi[(size_t)Nn * KS2], g_a2lo[(size_t)Nn * KS2];
__device__ __nv_bfloat16 g_w2hi[(size_t)HID2 * KS2], g_w2lo[(size_t)HID2 * KS2];

// ---------------- portable PTX helpers (sm_80+ ISA only) ----------------
__device__ __forceinline__ uint32_t smem_u32(const void* p) {
    uint32_t a;
    asm("{ .reg .u64 t; cvta.to.shared.u64 t, %1; cvt.u32.u64 %0, t; }"
        : "=r"(a) : "l"(p));
    return a;
}
__device__ __forceinline__ void cp16(uint32_t dst, const void* src, int sz) {
    asm volatile("cp.async.cg.shared.global [%0], [%1], 16, %2;"
                 :: "r"(dst), "l"(src), "r"(sz) : "memory");
}
__device__ __forceinline__ void cp_commit() {
    asm volatile("cp.async.commit_group;" ::: "memory");
}
template<int W> __device__ __forceinline__ void cp_wait() {
    asm volatile("cp.async.wait_group %0;" :: "n"(W) : "memory");
}
__device__ __forceinline__ void ldsm_x4(uint32_t& r0, uint32_t& r1, uint32_t& r2,
                                        uint32_t& r3, uint32_t addr) {
    asm volatile("ldmatrix.sync.aligned.m8n8.x4.shared.b16 {%0,%1,%2,%3}, [%4];"
                 : "=r"(r0), "=r"(r1), "=r"(r2), "=r"(r3) : "r"(addr));
}
__device__ __forceinline__ void mma16816(float* c, const uint32_t* a, const uint32_t* b) {
    asm volatile("mma.sync.aligned.m16n8k16.row.col.f32.bf16.bf16.f32 "
                 "{%0,%1,%2,%3}, {%4,%5,%6,%7}, {%8,%9}, {%0,%1,%2,%3};"
                 : "+f"(c[0]), "+f"(c[1]), "+f"(c[2]), "+f"(c[3])
                 : "r"(a[0]), "r"(a[1]), "r"(a[2]), "r"(a[3]), "r"(b[0]), "r"(b[1]));
}

// ---------------- 3-term split GEMM: C = (Ahi+Alo)*(Bhi+Blo)^T (drop lo*lo) ----------------
// Block 128x128x32, 2-stage cp.async, 8 warps of 64x32 warp tiles.
#define SROW 40
#define TILE_B16 (128 * SROW)            // one 128x32 tile (padded), b16 units
#define STAGE_B16 (4 * TILE_B16)         // Ahi|Alo|Bhi|Blo
#define SMEM_GEMM_BYTES (2 * STAGE_B16 * 2)

template<int Kp, int Ntot>
__device__ __forceinline__ void mma_gemm_body(const __nv_bfloat16* __restrict__ Ahi,
                                              const __nv_bfloat16* __restrict__ Alo,
                                              const __nv_bfloat16* __restrict__ Bhi,
                                              const __nv_bfloat16* __restrict__ Blo,
                                              float* __restrict__ C, int M)
{
    extern __shared__ __align__(16) __nv_bfloat16 smem[];
    const uint32_t sbase = smem_u32(smem);
    const int tid = threadIdx.x;
    const int wid = tid >> 5, lane = tid & 31;
    const int wm = wid & 1, wn = wid >> 1;      // 2 x 4 warp grid
    const int m0 = blockIdx.y * 128, n0 = blockIdx.x * 128;
    const int NC = Kp / 32;

    float acc[4][4][4];
#pragma unroll
    for (int i = 0; i < 4; i++)
#pragma unroll
        for (int j = 0; j < 4; j++)
#pragma unroll
            for (int q = 0; q < 4; q++) acc[i][j][q] = 0.f;

    const int lr = tid >> 2;             // 0..63
    const int lc = (tid & 3) * 8;        // 0,8,16,24

#define LOADC(c)                                                                  \
    {                                                                             \
        const int s_ = (c) & 1;                                                   \
        const int k0_ = (c) * 32;                                                 \
        const uint32_t st_ = sbase + (uint32_t)(s_ * STAGE_B16) * 2u;             \
        _Pragma("unroll")                                                         \
        for (int p = 0; p < 2; p++) {                                             \
            const int row = lr + p * 64;                                          \
            const uint32_t off = (uint32_t)(row * SROW + lc) * 2u;                \
            const int m = m0 + row;                                               \
            const int mc = m < M ? m : (M - 1);                                   \
            const int av = m < M ? 16 : 0;                                        \
            cp16(st_ + off,                Ahi + (size_t)mc * Kp + k0_ + lc, av); \
            cp16(st_ + TILE_B16 * 2u + off, Alo + (size_t)mc * Kp + k0_ + lc, av);\
            const size_t bo = (size_t)(n0 + row) * Kp + k0_ + lc;                 \
            cp16(st_ + TILE_B16 * 4u + off, Bhi + bo, 16);                        \
            cp16(st_ + TILE_B16 * 6u + off, Blo + bo, 16);                        \
        }                                                                         \
        cp_commit();                                                              \
    }

    LOADC(0);
    if (NC > 1) LOADC(1);

    for (int c = 0; c < NC; c++) {
        if (c + 1 < NC) cp_wait<1>(); else cp_wait<0>();
        __syncthreads();

        const int s = c & 1;
        const uint32_t sAh = sbase + (uint32_t)(s * STAGE_B16) * 2u;
        const uint32_t sAl = sAh + TILE_B16 * 2u;
        const uint32_t sBh = sAh + TILE_B16 * 4u;
        const uint32_t sBl = sAh + TILE_B16 * 6u;

#pragma unroll
        for (int ks = 0; ks < 2; ks++) {
            const int kk = ks * 16;
            const uint32_t arow = (uint32_t)((wm * 64 + (lane & 15)) * SROW
                                             + kk + ((lane >> 4) << 3)) * 2u;
            uint32_t afh[4][4], afl[4][4];
#pragma unroll
            for (int mt = 0; mt < 4; mt++) {
                const uint32_t ao = arow + (uint32_t)(mt * 16 * SROW) * 2u;
                ldsm_x4(afh[mt][0], afh[mt][1], afh[mt][2], afh[mt][3], sAh + ao);
                ldsm_x4(afl[mt][0], afl[mt][1], afl[mt][2], afl[mt][3], sAl + ao);
            }
            uint32_t bfh[4][2], bfl[4][2];
#pragma unroll
            for (int g = 0; g < 2; g++) {
                const uint32_t bo = (uint32_t)((wn * 32 + g * 16 + (lane & 7)
                                    + ((lane >> 4) << 3)) * SROW
                                    + kk + (((lane >> 3) & 1) << 3)) * 2u;
                uint32_t r0, r1, r2, r3;
                ldsm_x4(r0, r1, r2, r3, sBh + bo);
                bfh[2 * g][0] = r0; bfh[2 * g][1] = r1;
                bfh[2 * g + 1][0] = r2; bfh[2 * g + 1][1] = r3;
                ldsm_x4(r0, r1, r2, r3, sBl + bo);
                bfl[2 * g][0] = r0; bfl[2 * g][1] = r1;
                bfl[2 * g + 1][0] = r2; bfl[2 * g + 1][1] = r3;
            }
#pragma unroll
            for (int mt = 0; mt < 4; mt++)
#pragma unroll
                for (int nt = 0; nt < 4; nt++) {
                    mma16816(acc[mt][nt], afh[mt], bfh[nt]);
                    mma16816(acc[mt][nt], afh[mt], bfl[nt]);
                    mma16816(acc[mt][nt], afl[mt], bfh[nt]);
                }
        }
        __syncthreads();
        if (c + 2 < NC) LOADC(c + 2);
    }
#undef LOADC

    // epilogue
#pragma unroll
    for (int mt = 0; mt < 4; mt++) {
        const int r0 = m0 + wm * 64 + mt * 16 + (lane >> 2);
#pragma unroll
        for (int nt = 0; nt < 4; nt++) {
            const int cc = n0 + wn * 32 + nt * 8 + (lane & 3) * 2;
            if (r0 < M) {
                C[(size_t)r0 * Ntot + cc]     = acc[mt][nt][0];
                C[(size_t)r0 * Ntot + cc + 1] = acc[mt][nt][1];
            }
            if (r0 + 8 < M) {
                C[(size_t)(r0 + 8) * Ntot + cc]     = acc[mt][nt][2];
                C[(size_t)(r0 + 8) * Ntot + cc + 1] = acc[mt][nt][3];
            }
        }
    }
}

__global__ void __launch_bounds__(256) gemm1_mma() {
    mma_gemm_body<KS1, HID>(g_xhi, g_xlo, g_w1hi, g_w1lo, g_h1, Nn);
}
__global__ void __launch_bounds__(256) gemm2_mma() {
    mma_gemm_body<KS2, HID2>(g_a2hi, g_a2lo, g_w2hi, g_w2lo, g_h2, Nn);
}

// ---------------- fp32 -> bf16 hi/lo split ----------------
__device__ __forceinline__ void split_bf16(float f, __nv_bfloat16& hi, __nv_bfloat16& lo) {
    hi = __float2bfloat16(f);
    lo = __float2bfloat16(f - __bfloat162float(hi));
}

__global__ void conv_x_kernel(const float* __restrict__ x) {
    int i = blockIdx.x * blockDim.x + threadIdx.x;
    if (i >= Nn * KS1) return;
    int n = i / KS1, k = i % KS1;
    float f = (k < Fin) ? x[(size_t)n * Fin + k] : 0.f;
    __nv_bfloat16 hi, lo; split_bf16(f, hi, lo);
    g_xhi[i] = hi;
    g_xlo[i] = lo;
}

// W [K][N] -> [N][Kp] hi/lo (tiled transpose, zero-pad k >= K)
template<int K, int KPv, int N>
__device__ __forceinline__ void convT_body(const float* __restrict__ in,
                                           __nv_bfloat16* __restrict__ hip,
                                           __nv_bfloat16* __restrict__ lop)
{
    __shared__ float t[32][33];
    const int kb = blockIdx.x * 32, nb = blockIdx.y * 32;
    const int tx = threadIdx.x, ty = threadIdx.y;
#pragma unroll
    for (int j = 0; j < 4; j++) {
        int k = kb + ty + j * 8;
        t[ty + j * 8][tx] = (k < K) ? in[(size_t)k * N + nb + tx] : 0.f;
    }
    __syncthreads();
#pragma unroll
    for (int j = 0; j < 4; j++) {
        int n = nb + ty + j * 8;
        int k = kb + tx;
        __nv_bfloat16 hi, lo;
        split_bf16(t[tx][ty + j * 8], hi, lo);
        hip[(size_t)n * KPv + k] = hi;
        lop[(size_t)n * KPv + k] = lo;
    }
}
__global__ void convT1_kernel(const float* __restrict__ W1) {
    convT_body<Fin, KS1, HID>(W1, g_w1hi, g_w1lo);
}
__global__ void convT2_kernel(const float* __restrict__ W2) {
    convT_body<HID, KS2, HID2>(W2, g_w2hi, g_w2lo);
}

// ---------------- edge decode (int32/int64 auto-detect) ----------------
__global__ void decode_edges_kernel(const unsigned int* __restrict__ w)
{
    __shared__ int is64;
    if (threadIdx.x == 0) {
        unsigned int nz = 0u;
#pragma unroll
        for (int i = 1; i < 257; i += 2) nz |= w[i];
        is64 = (nz == 0u) ? 1 : 0;
    }
    __syncthreads();
    int e = blockIdx.x * blockDim.x + threadIdx.x;
    if (e >= Ee) return;
    int s, d;
    if (is64) { s = (int)w[2 * e]; d = (int)w[2 * (Ee + e)]; }
    else      { s = (int)w[e];     d = (int)w[Ee + e]; }
    s = s < 0 ? 0 : (s >= Nn ? Nn - 1 : s);
    d = d < 0 ? 0 : (d >= Nn ? Nn - 1 : d);
    g_src[e] = s;
    g_dst[e] = d;
}

// ---------------- CSR build ----------------
__global__ void zero_deg_kernel() {
    int i = blockIdx.x * blockDim.x + threadIdx.x;
    if (i < Nn) g_deg[i] = 0;
}
__global__ void count_deg_kernel() {
    int e = blockIdx.x * blockDim.x + threadIdx.x;
    if (e < Ee) atomicAdd(&g_deg[g_dst[e]], 1);
}
__global__ void scan_kernel() {
    __shared__ int sd[1024];
    __shared__ int carry_s;
    const int tid = threadIdx.x;
    if (tid == 0) carry_s = 0;
    __syncthreads();
    for (int c0 = 0; c0 < Nn; c0 += 1024) {
        int idx = c0 + tid;
        int v = (idx < Nn) ? g_deg[idx] : 0;
        sd[tid] = v;
        __syncthreads();
        for (int off = 1; off < 1024; off <<= 1) {
            int t = (tid >= off) ? sd[tid - off] : 0;
            __syncthreads();
            sd[tid] += t;
            __syncthreads();
        }
        int incl = sd[tid];
        int excl = carry_s + incl - v;
        if (idx < Nn) { g_rowptr[idx] = excl; g_cursor[idx] = excl; }
        __syncthreads();
        if (tid == 1023) carry_s += incl;
        __syncthreads();
    }
    if (tid == 0) g_rowptr[Nn] = carry_s;
}
__global__ void fill_csr_kernel() {
    int e = blockIdx.x * blockDim.x + threadIdx.x;
    if (e >= Ee) return;
    int pos = atomicAdd(&g_cursor[g_dst[e]], 1);
    g_esrc[pos] = g_src[e];
}

// ---------------- per-(node,head) attention logits ----------------
__device__ __forceinline__ void alphas_body(const float* __restrict__ h,
                                            const float* __restrict__ a_s,
                                            const float* __restrict__ a_d, int C)
{
    int w = (blockIdx.x * blockDim.x + threadIdx.x) >> 5;
    int lane = threadIdx.x & 31;
    if (w >= Nn * Hh) return;
    int n = w / Hh, hd = w % Hh;
    const float* hp  = h   + (long long)n * Hh * C + hd * C;
    const float* asp = a_s + hd * C;
    const float* adp = a_d + hd * C;
    float ss = 0.f, sd = 0.f;
    for (int c = lane; c < C; c += 32) {
        float v = hp[c];
        ss = fmaf(v, asp[c], ss);
        sd = fmaf(v, adp[c], sd);
    }
#pragma unroll
    for (int o = 16; o > 0; o >>= 1) {
        ss += __shfl_xor_sync(0xffffffffu, ss, o);
        sd += __shfl_xor_sync(0xffffffffu, sd, o);
    }
    if (lane == 0) { g_as[w] = ss; g_ad[w] = sd; }
}
__global__ void alphas1_kernel(const float* __restrict__ a_s, const float* __restrict__ a_d) {
    alphas_body(g_h1, a_s, a_d, C1c);
}
__global__ void alphas2_kernel(const float* __restrict__ a_s, const float* __restrict__ a_d) {
    alphas_body(g_h2, a_s, a_d, C2c);
}

// ---------------- fused online-softmax aggregation ----------------
// Layer 1: one warp per (dst, head); 32 lanes x float4 = 128 channels.
// Output: relu(agg + b1) split to bf16 hi/lo (the layer-2 GEMM A operand).
__global__ void agg1_kernel(const float* __restrict__ b1)
{
    int w = (blockIdx.x * blockDim.x + threadIdx.x) >> 5;
    int lane = threadIdx.x & 31;
    if (w >= Nn * Hh) return;
    int d = w / Hh, h = w % Hh;
    const float ad = g_ad[w];

    // self loop
    float vs = g_as[w] + ad;
    vs = vs > 0.f ? vs : NEG * vs;
    float m = vs, den = 1.f;
    float4 acc = ((const float4*)(g_h1 + (size_t)d * HID + h * C1c))[lane];

    const int beg = g_rowptr[d], end = g_rowptr[d + 1];
    for (int j = beg; j < end; j++) {
        int s = g_esrc[j];
        float v = g_as[s * Hh + h] + ad;
        v = v > 0.f ? v : NEG * v;
        float4 hv = ((const float4*)(g_h1 + (size_t)s * HID + h * C1c))[lane];
        if (v <= m) {
            float wg = __expf(v - m);
            den += wg;
            acc.x = fmaf(wg, hv.x, acc.x);
            acc.y = fmaf(wg, hv.y, acc.y);
            acc.z = fmaf(wg, hv.z, acc.z);
            acc.w = fmaf(wg, hv.w, acc.w);
        } else {
            float sc = __expf(m - v);
            den = fmaf(den, sc, 1.f);
            acc.x = fmaf(acc.x, sc, hv.x);
            acc.y = fmaf(acc.y, sc, hv.y);
            acc.z = fmaf(acc.z, sc, hv.z);
            acc.w = fmaf(acc.w, sc, hv.w);
            m = v;
        }
    }
    const float inv = 1.f / den;
    const int f = h * C1c + lane * 4;
    const size_t ob = (size_t)d * HID + f;
    float o[4] = { acc.x * inv + b1[f], acc.y * inv + b1[f + 1],
                   acc.z * inv + b1[f + 2], acc.w * inv + b1[f + 3] };
#pragma unroll
    for (int q = 0; q < 4; q++) {
        float r = o[q] > 0.f ? o[q] : 0.f;
        __nv_bfloat16 hi, lo; split_bf16(r, hi, lo);
        g_a2hi[ob + q] = hi;
        g_a2lo[ob + q] = lo;
    }
}

// Layer 2: one warp per (dst, head); 32 lanes x float2 = 64 channels -> g_agg2 (incl self).
__global__ void agg2_kernel()
{
    int w = (blockIdx.x * blockDim.x + threadIdx.x) >> 5;
    int lane = threadIdx.x & 31;
    if (w >= Nn * Hh) return;
    int d = w / Hh, h = w % Hh;
    const float ad = g_ad[w];

    float vs = g_as[w] + ad;
    vs = vs > 0.f ? vs : NEG * vs;
    float m = vs, den = 1.f;
    float2 acc = ((const float2*)(g_h2 + (size_t)d * HID2 + h * C2c))[lane];

    const int beg = g_rowptr[d], end = g_rowptr[d + 1];
    for (int j = beg; j < end; j++) {
        int s = g_esrc[j];
        float v = g_as[s * Hh + h] + ad;
        v = v > 0.f ? v : NEG * v;
        float2 hv = ((const float2*)(g_h2 + (size_t)s * HID2 + h * C2c))[lane];
        if (v <= m) {
            float wg = __expf(v - m);
            den += wg;
            acc.x = fmaf(wg, hv.x, acc.x);
            acc.y = fmaf(wg, hv.y, acc.y);
        } else {
            float sc = __expf(m - v);
            den = fmaf(den, sc, 1.f);
            acc.x = fmaf(acc.x, sc, hv.x);
            acc.y = fmaf(acc.y, sc, hv.y);
            m = v;
        }
    }
    const float inv = 1.f / den;
    float2* op = (float2*)(g_agg2 + (size_t)d * HID2 + h * C2c);
    op[lane] = make_float2(acc.x * inv, acc.y * inv);
}

// ---------------- final: mean over heads + bias + relu ----------------
__global__ void final2_kernel(const float* __restrict__ b2, float* __restrict__ out)
{
    int i = blockIdx.x * blockDim.x + threadIdx.x;
    if (i >= Nn * C2c) return;
    int n = i / C2c, l = i % C2c;
    float sum = 0.f;
#pragma unroll
    for (int hh = 0; hh < Hh; hh++)
        sum += g_agg2[(size_t)n * HID2 + hh * C2c + l];
    float v = sum * (1.0f / Hh) + b2[l];
    out[i] = v > 0.f ? v : 0.f;
}

// ---------------- launch ----------------
extern "C" void kernel_launch(void* const* d_in, const int* in_sizes, int n_in,
                              void* d_out, int out_size)
{
    const float*        x      = (const float*)d_in[0];
    const unsigned int* ei_raw = (const unsigned int*)d_in[1];
    const float*        W1     = (const float*)d_in[2];
    const float*        a_src1 = (const float*)d_in[3];
    const float*        a_dst1 = (const float*)d_in[4];
    const float*        b1     = (const float*)d_in[5];
    const float*        W2     = (const float*)d_in[6];
    const float*        a_src2 = (const float*)d_in[7];
    const float*        a_dst2 = (const float*)d_in[8];
    const float*        b2     = (const float*)d_in[9];
    float* out = (float*)d_out;

    const int TB = 256;
    static bool attr_done = false;
    if (!attr_done) {
        cudaFuncSetAttribute(gemm1_mma, cudaFuncAttributeMaxDynamicSharedMemorySize, SMEM_GEMM_BYTES);
        cudaFuncSetAttribute(gemm2_mma, cudaFuncAttributeMaxDynamicSharedMemorySize, SMEM_GEMM_BYTES);
        attr_done = true;
    }

    // ---------- edge decode + CSR ----------
    decode_edges_kernel<<<(Ee + TB - 1) / TB, TB>>>(ei_raw);
    zero_deg_kernel<<<(Nn + TB - 1) / TB, TB>>>();
    count_deg_kernel<<<(Ee + TB - 1) / TB, TB>>>();
    scan_kernel<<<1, 1024>>>();
    fill_csr_kernel<<<(Ee + TB - 1) / TB, TB>>>();

    // ---------- operand prep ----------
    conv_x_kernel<<<(Nn * KS1 + TB - 1) / TB, TB>>>(x);
    {
        dim3 blk(32, 8);
        convT1_kernel<<<dim3(KS1 / 32, HID / 32), blk>>>(W1);
        convT2_kernel<<<dim3(KS2 / 32, HID2 / 32), blk>>>(W2);
    }

    // ---------- layer 1 ----------
    gemm1_mma<<<dim3(HID / 128, (Nn + 127) / 128), 256, SMEM_GEMM_BYTES>>>();
    alphas1_kernel<<<(Nn * Hh * 32 + TB - 1) / TB, TB>>>(a_src1, a_dst1);
    agg1_kernel<<<(Nn * Hh * 32 + TB - 1) / TB, TB>>>(b1);

    // ---------- layer 2 ----------
    gemm2_mma<<<dim3(HID2 / 128, (Nn + 127) / 128), 256, SMEM_GEMM_BYTES>>>();
    alphas2_kernel<<<(Nn * Hh * 32 + TB - 1) / TB, TB>>>(a_src2, a_dst2);
    agg2_kernel<<<(Nn * Hh * 32 + TB - 1) / TB, TB>>>();
    final2_kernel<<<(Nn * C2c + TB - 1) / TB, TB>>>(b2, out);
}